// round 17
// baseline (speedup 1.0000x reference)
#include <cuda_runtime.h>
#include <cuda_fp16.h>
#include <math.h>
#include <stdint.h>
#include <stddef.h>

// ============================================================================
// TripletGNN:
//   qkv(n,t) = P[ci0] + Q[ci1] + g(cos_values(n,t))
//   g tabulated at 4097 points, nearest-neighbor, fp16.
//   [P|Q] = xh @ Bh, pure fp16 mma.sync with fp32 accum.
//   PQ stored fp16. Scores = qh * kh. Cross-stream prep overlap.
// ============================================================================

#define MAXN 40000
#define TAB_N 4096
#define APAD 40
#define QP 264

typedef unsigned long long u64;

__device__ __half g_PQh[(size_t)(MAXN + 1) * 1536];
__device__ float  g_WaT64[64 * 768];
__device__ __half g_TabH[(size_t)(TAB_N + 1) * 768];
__device__ __half g_Ah[(size_t)MAXN * 256];
__device__ __half g_Bh[1536 * 256];

// ------------------------------------------------------------ f32x2 helpers -
__device__ __forceinline__ u64 ffma2(u64 a, u64 b, u64 c) {
    u64 d;
    asm("fma.rn.f32x2 %0, %1, %2, %3;" : "=l"(d) : "l"(a), "l"(b), "l"(c));
    return d;
}
__device__ __forceinline__ u64 fadd2(u64 a, u64 b) {
    u64 d;
    asm("add.rn.f32x2 %0, %1, %2;" : "=l"(d) : "l"(a), "l"(b));
    return d;
}
__device__ __forceinline__ u64 pack2(float lo, float hi) {
    u64 d;
    asm("mov.b64 %0, {%1, %2};" : "=l"(d) : "f"(lo), "f"(hi));
    return d;
}
__device__ __forceinline__ float lo32(u64 v) {
    return __uint_as_float((unsigned)(v & 0xffffffffull));
}
__device__ __forceinline__ float hi32(u64 v) {
    return __uint_as_float((unsigned)(v >> 32));
}

// ------------------------------------------------------------ mma helpers ---
__device__ __forceinline__ void ldsm4(uint32_t& r0, uint32_t& r1,
                                      uint32_t& r2, uint32_t& r3,
                                      uint32_t addr) {
    asm volatile("ldmatrix.sync.aligned.m8n8.x4.shared.b16 {%0,%1,%2,%3}, [%4];"
                 : "=r"(r0), "=r"(r1), "=r"(r2), "=r"(r3) : "r"(addr));
}
__device__ __forceinline__ void mma16816(float* d, const uint32_t* a,
                                         uint32_t b0, uint32_t b1) {
    asm volatile(
        "mma.sync.aligned.m16n8k16.row.col.f32.f16.f16.f32 "
        "{%0,%1,%2,%3}, {%4,%5,%6,%7}, {%8,%9}, {%0,%1,%2,%3};"
        : "+f"(d[0]), "+f"(d[1]), "+f"(d[2]), "+f"(d[3])
        : "r"(a[0]), "r"(a[1]), "r"(a[2]), "r"(a[3]), "r"(b0), "r"(b1));
}
__device__ __forceinline__ void cp_async16(uint32_t dst, const void* src,
                                           int src_bytes) {
    asm volatile("cp.async.cg.shared.global [%0], [%1], 16, %2;"
                 :: "r"(dst), "l"(src), "r"(src_bytes));
}
#define CP_COMMIT() asm volatile("cp.async.commit_group;" ::: "memory")
#define CP_WAIT2()  asm volatile("cp.async.wait_group 2;" ::: "memory")
#define CP_WAIT0()  asm volatile("cp.async.wait_group 0;" ::: "memory")

// ------------------------------------------------------------------- prep ---
__global__ void prep_misc_kernel(const float* __restrict__ W,
                                 const float* __restrict__ bias, int N) {
    int idx = blockIdx.x * blockDim.x + threadIdx.x;
    const int WA_SZ = 64 * 768;
    const int B_SZ = 1536 * 256;
    if (idx < WA_SZ) {
        int m = idx / 768, j = idx % 768;
        g_WaT64[idx] = W[j * 576 + 512 + m];
    } else if (idx < WA_SZ + B_SZ) {
        int r = idx - WA_SZ;
        int j = r >> 8, k = r & 255;
        float v = (j < 768) ? W[j * 576 + k] : W[(j - 768) * 576 + 256 + k];
        g_Bh[r] = __float2half(v);
    } else if (idx < WA_SZ + B_SZ + 1536) {
        int j = idx - (WA_SZ + B_SZ);
        g_PQh[(size_t)N * 1536 + j] =
            __float2half((j < 768) ? bias[j] : 0.0f);
    }
}

// Fused, float4-vectorized: x -> Ah fp16; out[:,0:256]=x; [256:512]=0.
__global__ void fused_init_kernel(const float* __restrict__ x,
                                  float* __restrict__ out, int total4) {
    int idx = blockIdx.x * blockDim.x + threadIdx.x;
    if (idx < total4) {
        float4 v = *(const float4*)(x + idx * 4);
        __half2 hi01 = __halves2half2(__float2half(v.x), __float2half(v.y));
        __half2 hi23 = __halves2half2(__float2half(v.z), __float2half(v.w));
        *(uint2*)(g_Ah + idx * 4) =
            make_uint2(*(unsigned*)&hi01, *(unsigned*)&hi23);
        int r = idx >> 6, c4 = idx & 63;
        *(float4*)(out + (size_t)r * 512 + c4 * 4) = v;
        *(float4*)(out + (size_t)r * 512 + 256 + c4 * 4) =
            make_float4(0.f, 0.f, 0.f, 0.f);
    }
}

// --------------------------------------------------------- angle table ------
__global__ __launch_bounds__(256)
void table_build_kernel() {
    __shared__ float S[64][65];
    const int tid = threadIdx.x;
    const int e0 = blockIdx.x * 64;
    const int j = blockIdx.y * 256 + tid;

    for (int idx = tid; idx < 64 * 64; idx += 256) {
        int el = idx >> 6, m = idx & 63;
        int e = e0 + el;
        float val = 0.0f;
        if (e <= TAB_N) {
            int mp = m >> 1;
            float u = (float)e * (2.0f / TAB_N) - 1.0f;
            float om = u * expf(-0.28782313662425572f * (float)mp);
            float s, c;
            sincosf(om, &s, &c);
            val = (m & 1) ? c : s;
        }
        S[idx >> 6][m] = val;
    }
    __syncthreads();

    float acc[64];
#pragma unroll
    for (int el = 0; el < 64; el++) acc[el] = 0.0f;
#pragma unroll 8
    for (int m = 0; m < 64; m++) {
        float w = g_WaT64[m * 768 + j];
#pragma unroll
        for (int el = 0; el < 64; el++) acc[el] = fmaf(S[el][m], w, acc[el]);
    }
#pragma unroll
    for (int el = 0; el < 64; el++) {
        int e = e0 + el;
        if (e <= TAB_N) g_TabH[(size_t)e * 768 + j] = __float2half(acc[el]);
    }
}

// ------------------- cp.async 3-stage pure-fp16 GEMM ------------------------
#define OFF_AH 0
#define OFF_BH 10240
#define STAGE_B 20480
#define GEMM_SMEM_B (3 * STAGE_B)

__global__ __launch_bounds__(256, 2)
void gemm_mma_kernel(const float* __restrict__ bias, int M) {
    extern __shared__ __half smem_h[];
    const int tid = threadIdx.x;
    const int wid = tid >> 5;
    const int lid = tid & 31;
    const int wm = wid >> 2;
    const int wn = wid & 3;
    const int row0 = blockIdx.y * 128;
    const int col0 = blockIdx.x * 128;
    uint32_t sbase = (uint32_t)__cvta_generic_to_shared(smem_h);

    float acc[4][4][4];
#pragma unroll
    for (int i = 0; i < 4; i++)
#pragma unroll
        for (int jq = 0; jq < 4; jq++)
#pragma unroll
            for (int r = 0; r < 4; r++) acc[i][jq][r] = 0.0f;

    const int lrow = lid & 15;
    const int lkoff = (lid >> 4) * 16;

#define ISSUE(ST, KK)                                                         \
    {                                                                         \
        uint32_t stb = sbase + (ST) * STAGE_B;                                \
        _Pragma("unroll") for (int l = 0; l < 2; l++) {                       \
            int fid = tid + l * 256;                                          \
            int r = fid >> 2, q = fid & 3;                                    \
            uint32_t d0 = stb + (uint32_t)(r * APAD + q * 8) * 2;             \
            int grow = row0 + r;                                              \
            int asz = (grow < M) ? 16 : 0;                                    \
            size_t asrc = (size_t)(grow < M ? grow : 0) * 256 + (KK) + q * 8; \
            cp_async16(d0 + OFF_AH, g_Ah + asrc, asz);                        \
            size_t bsrc = (size_t)(col0 + r) * 256 + (KK) + q * 8;            \
            cp_async16(d0 + OFF_BH, g_Bh + bsrc, 16);                         \
        }                                                                     \
        CP_COMMIT();                                                          \
    }

    ISSUE(0, 0)
    ISSUE(1, 32)
    for (int kt = 0; kt < 8; kt++) {
        if (kt < 6) {
            ISSUE((kt + 2) % 3, (kt + 2) * 32)
            CP_WAIT2();
        } else {
            CP_WAIT0();
        }
        __syncthreads();

        uint32_t stb = sbase + (kt % 3) * STAGE_B;
#pragma unroll
        for (int k16 = 0; k16 < 32; k16 += 16) {
            uint32_t bh[2][4];
#pragma unroll
            for (int nt = 0; nt < 2; nt++) {
                uint32_t boff = stb + OFF_BH +
                    (uint32_t)((wn * 32 + nt * 16 + lrow) * APAD + k16) * 2 +
                    lkoff;
                ldsm4(bh[nt][0], bh[nt][1], bh[nt][2], bh[nt][3], boff);
            }
#pragma unroll
            for (int mt = 0; mt < 4; mt++) {
                uint32_t aoff = stb + OFF_AH +
                    (uint32_t)((wm * 64 + mt * 16 + lrow) * APAD + k16) * 2 +
                    lkoff;
                uint32_t ah[4];
                ldsm4(ah[0], ah[1], ah[2], ah[3], aoff);
#pragma unroll
                for (int n = 0; n < 4; n++) {
                    int nt = n >> 1, jj = n & 1;
                    mma16816(acc[mt][n], ah, bh[nt][jj], bh[nt][jj + 2]);
                }
            }
        }
        __syncthreads();
    }
#undef ISSUE

#pragma unroll
    for (int mt = 0; mt < 4; mt++) {
#pragma unroll
        for (int n = 0; n < 4; n++) {
            int gcol = col0 + wn * 32 + (n >> 1) * 16 + (n & 1) * 8 +
                       (lid & 3) * 2;
            float bx = 0.f, by = 0.f;
            if (gcol < 768) { bx = bias[gcol]; by = bias[gcol + 1]; }
            int r0g = row0 + wm * 64 + mt * 16 + (lid >> 2);
            if (r0g < M) {
                __half2 o = __halves2half2(__float2half(acc[mt][n][0] + bx),
                                           __float2half(acc[mt][n][1] + by));
                *(__half2*)(g_PQh + (size_t)r0g * 1536 + gcol) = o;
            }
            if (r0g + 8 < M) {
                __half2 o = __halves2half2(__float2half(acc[mt][n][2] + bx),
                                           __float2half(acc[mt][n][3] + by));
                *(__half2*)(g_PQh + (size_t)(r0g + 8) * 1536 + gcol) = o;
            }
        }
    }
}

// --------------------------------------------------------------- main ------
__global__ __launch_bounds__(256, 6)
void triplet_main_kernel(const float* __restrict__ pos,
                         const int* __restrict__ anchor_idx,
                         const int* __restrict__ corner_idx,
                         const int* __restrict__ masks,
                         float* __restrict__ out,
                         int N, int write_masks) {
    __shared__ __align__(16) __half qh[16][QP];
    __shared__ __align__(16) __half kh[16][QP];
    __shared__ __align__(16) float sSp[4][16][17];
    __shared__ __align__(16) float red[16][16];
    __shared__ __align__(16) u64 vp[2][128];
    __shared__ int ci0s[16], ci1s[16];
    __shared__ int tIdx[16];
    __shared__ float maskf[16], wsh[16];

    const int n = blockIdx.x;
    const int tid = threadIdx.x;
    const int cp = tid & 127;
    const int th = tid >> 7;
    const int wid = tid >> 5;
    const int lid = tid & 31;
    const int a_idx = anchor_idx[n];

    // ---- Phase 0: triplet geometry + table index (nearest) ----
    if (tid < 16) {
        int t = tid;
        float ax = 0.f, ay = 0.f;
        if (a_idx >= 0 && a_idx < N) {
            ax = pos[(size_t)a_idx * 3 + 0];
            ay = pos[(size_t)a_idx * 3 + 1];
        }
        int i0 = corner_idx[(size_t)n * 32 + 2 * t];
        int i1 = corner_idx[(size_t)n * 32 + 2 * t + 1];
        float p0x = 0.f, p0y = 0.f, p1x = 0.f, p1y = 0.f;
        if (i0 >= 0 && i0 < N) { p0x = pos[(size_t)i0 * 3]; p0y = pos[(size_t)i0 * 3 + 1]; }
        if (i1 >= 0 && i1 < N) { p1x = pos[(size_t)i1 * 3]; p1y = pos[(size_t)i1 * 3 + 1]; }
        float v0x = p0x - ax, v0y = p0y - ay;
        float v1x = p1x - ax, v1y = p1y - ay;
        float dot = v0x * v1x + v0y * v1y;
        float n0 = sqrtf(v0x * v0x + v0y * v0y);
        float n1 = sqrtf(v1x * v1x + v1y * v1y);
        float cosv = dot / (n0 * n1 + 1e-6f);
        float sinz = v0x * v1y - v0y * v1x;
        bool reorder = sinz < 0.0f;
        ci0s[t] = reorder ? i1 : i0;
        ci1s[t] = reorder ? i0 : i1;
        float s = (cosv + 1.0f) * (TAB_N * 0.5f);
        int ti = (int)floorf(s + 0.5f);
        if (ti < 0) ti = 0;
        if (ti > TAB_N) ti = TAB_N;
        tIdx[t] = ti;
        int mb = masks[(size_t)n * 16 + t];
        maskf[t] = (mb != 0) ? 1.0f : 0.0f;
        if (write_masks) {
            float newsin = reorder ? -sinz : sinz;
            out[(size_t)N * 512 + (size_t)n * 16 + t] =
                ((newsin < -1e-6f) && (mb != 0)) ? 1.0f : 0.0f;
        }
    }
    __syncthreads();

    // ---- Phase 1: fp16 gathers + NN table; stage qh, kh ----
    u64 v2[8];
#pragma unroll
    for (int tt = 0; tt < 8; tt++) {
        int t = 8 * th + tt;
        int i0 = ci0s[t]; if (i0 < 0 || i0 > N) i0 = N;
        int i1 = ci1s[t]; if (i1 < 0 || i1 > N) i1 = N;
        const __half2* r0 = (const __half2*)(g_PQh + (size_t)i0 * 1536);
        const __half2* r1 = (const __half2*)(g_PQh + (size_t)i1 * 1536 + 768);
        float2 pq = __half22float2(r0[cp]);
        float2 qq = __half22float2(r1[cp]);
        float2 pk = __half22float2(r0[128 + cp]);
        float2 qk = __half22float2(r1[128 + cp]);
        float2 pv = __half22float2(r0[256 + cp]);
        float2 qv = __half22float2(r1[256 + cp]);

        const __half2* T0 = (const __half2*)(g_TabH + (size_t)tIdx[t] * 768);
        float2 aq = __half22float2(T0[cp]);
        float2 ak = __half22float2(T0[128 + cp]);
        float2 av = __half22float2(T0[256 + cp]);

        float qx = pq.x + qq.x + aq.x;
        float qy = pq.y + qq.y + aq.y;
        float kx = pk.x + qk.x + ak.x;
        float ky = pk.y + qk.y + ak.y;
        float vx = pv.x + qv.x + av.x;
        float vy = pv.y + qv.y + av.y;

        *(__half2*)&qh[t][2 * cp] =
            __halves2half2(__float2half(qx), __float2half(qy));
        *(__half2*)&kh[t][2 * cp] =
            __halves2half2(__float2half(kx), __float2half(ky));
        v2[tt] = pack2(vx, vy);
    }
    __syncthreads();

    // ---- Phase 2: S = qh kh^T via mma, K split over warps 0-3 ----
    if (wid < 4) {
        const int lrow = lid & 15;
        const int lkoff = (lid >> 4) * 16;
        uint32_t qh_u = (uint32_t)__cvta_generic_to_shared(qh);
        uint32_t kh_u = (uint32_t)__cvta_generic_to_shared(kh);
        float acc[2][4];
#pragma unroll
        for (int jj = 0; jj < 2; jj++)
#pragma unroll
            for (int r = 0; r < 4; r++) acc[jj][r] = 0.0f;

        const int kbase = wid * 64;
#pragma unroll
        for (int kq = 0; kq < 64; kq += 16) {
            int k16 = kbase + kq;
            uint32_t off = (uint32_t)(lrow * QP + k16) * 2 + lkoff;
            uint32_t ah[4], bh[4];
            ldsm4(ah[0], ah[1], ah[2], ah[3], qh_u + off);
            ldsm4(bh[0], bh[1], bh[2], bh[3], kh_u + off);
#pragma unroll
            for (int jj = 0; jj < 2; jj++)
                mma16816(acc[jj], ah, bh[jj], bh[jj + 2]);
        }
        int r0 = lid >> 2;
        int c0 = (lid & 3) * 2;
#pragma unroll
        for (int jj = 0; jj < 2; jj++) {
            sSp[wid][r0][jj * 8 + c0] = acc[jj][0];
            sSp[wid][r0][jj * 8 + c0 + 1] = acc[jj][1];
            sSp[wid][r0 + 8][jj * 8 + c0] = acc[jj][2];
            sSp[wid][r0 + 8][jj * 8 + c0 + 1] = acc[jj][3];
        }
    }
    __syncthreads();

    // ---- Phase 3: softmax (sum the 4 K-partials first) ----
    {
        int aa = tid >> 4, bb = tid & 15;
        float sc = (sSp[0][aa][bb] + sSp[1][aa][bb] +
                    sSp[2][aa][bb] + sSp[3][aa][bb]) * 0.0625f;
        float mx = sc;
#pragma unroll
        for (int off = 8; off > 0; off >>= 1)
            mx = fmaxf(mx, __shfl_xor_sync(0xffffffffu, mx, off, 16));
        float e = expf(sc - mx);
        float sm = e;
#pragma unroll
        for (int off = 8; off > 0; off >>= 1)
            sm += __shfl_xor_sync(0xffffffffu, sm, off, 16);
        float attn = e / sm;
        red[aa][bb] = maskf[aa] * attn;
    }
    __syncthreads();

    // ---- Phase 4: fold mask-mean into per-k weights ----
    if (tid < 16) {
        float s = 0.0f, dn = 0.0f;
#pragma unroll
        for (int a2 = 0; a2 < 16; a2++) {
            s += red[a2][tid];
            dn += maskf[a2];
        }
        wsh[tid] = s / dn;
    }
    __syncthreads();

    // ---- Phase 5: mean over t, scatter ----
    {
        u64 part = pack2(0.f, 0.f);
#pragma unroll
        for (int tt = 0; tt < 8; tt++) {
            float w = wsh[8 * th + tt];
            part = ffma2(pack2(w, w), v2[tt], part);
        }
        vp[th][cp] = part;
        __syncthreads();
        if (th == 0) {
            u64 tot = fadd2(vp[0][cp], vp[1][cp]);
            if (a_idx >= 0 && a_idx < N) {
                float2 o;
                o.x = lo32(tot);
                o.y = hi32(tot);
                *(float2*)(out + (size_t)a_idx * 512 + 256 + 2 * cp) = o;
            }
        }
    }
}

// ----------------------------------------------------------------------------
extern "C" void kernel_launch(void* const* d_in, const int* in_sizes, int n_in,
                              void* d_out, int out_size) {
    if (n_in < 7) return;
    const float* x = (const float*)d_in[0];
    const float* pos = (const float*)d_in[1];
    const int* anchor = (const int*)d_in[2];
    const int* corner = (const int*)d_in[3];
    const int* masks = (const int*)d_in[4];
    const float* W = (const float*)d_in[5];
    const float* bias = (const float*)d_in[6];
    float* out = (float*)d_out;

    int N = in_sizes[0] / 256;
    if (N > MAXN) N = MAXN;
    int write_masks = (out_size >= N * 512 + N * 16) ? 1 : 0;

    // One-time infra (no device memory allocation involved).
    static cudaStream_t sA = nullptr, sB = nullptr;
    static cudaEvent_t evRoot = nullptr, evPrep = nullptr, evInit = nullptr,
                       evTab = nullptr;
    if (!sA) {
        cudaStreamCreateWithFlags(&sA, cudaStreamNonBlocking);
        cudaStreamCreateWithFlags(&sB, cudaStreamNonBlocking);
        cudaEventCreateWithFlags(&evRoot, cudaEventDisableTiming);
        cudaEventCreateWithFlags(&evPrep, cudaEventDisableTiming);
        cudaEventCreateWithFlags(&evInit, cudaEventDisableTiming);
        cudaEventCreateWithFlags(&evTab, cudaEventDisableTiming);
        cudaFuncSetAttribute(gemm_mma_kernel,
                             cudaFuncAttributeMaxDynamicSharedMemorySize,
                             GEMM_SMEM_B);
    }

    // Fork: prep on stream 0 (capture origin), init on sA.
    cudaEventRecord(evRoot, 0);
    cudaStreamWaitEvent(sA, evRoot, 0);

    const int prep_work = 64 * 768 + 1536 * 256 + 1536;
    prep_misc_kernel<<<(prep_work + 255) / 256, 256>>>(W, bias, N);
    cudaEventRecord(evPrep, 0);

    int total4 = N * 64;
    fused_init_kernel<<<(total4 + 255) / 256, 256, 0, sA>>>(x, out, total4);
    cudaEventRecord(evInit, sA);

    // table_build depends only on prep -> run on sB, overlapped with gemm.
    cudaStreamWaitEvent(sB, evPrep, 0);
    dim3 tg((TAB_N + 64) / 64, 3);
    table_build_kernel<<<tg, 256, 0, sB>>>();
    cudaEventRecord(evTab, sB);

    // gemm on stream 0: needs prep (in-order) + init (event).
    cudaStreamWaitEvent(0, evInit, 0);
    dim3 gg(12, (N + 127) / 128);
    gemm_mma_kernel<<<gg, 256, GEMM_SMEM_B>>>(bias, N);

    // triplet: needs gemm (in-order) + table (event).
    cudaStreamWaitEvent(0, evTab, 0);
    triplet_main_kernel<<<N, 256>>>(pos, anchor, corner, masks, out, N,
                                    write_masks);
}